// round 12
// baseline (speedup 1.0000x reference)
#include <cuda_runtime.h>
#include <cstdint>

// CostVolume2D: out[n, dy*9+dx, h, w] = mean_c f1[n,c,h,w] * f2pad[n,c,h+dy,w+dx]
// N=8, C=128, H=96, W=224, D=4 -> 81 channels. fp32.
//
// R12 = R8 staging structure (depth-2 cp.async, two syncs/chunk, precomputed
// descriptors — the proven-best schedule) + ulonglong2 pair loads +
// WAVE-QUANTIZATION FIX: dy split {3,2,2,2} across gridDim.z (z=N*4=32,
// grid=1344) so 1344/456 concurrent = 2.95 waves (was 1008/456=2.21 -> 3
// ragged waves). n-major z preserves L2 reuse.

#define N_ 8
#define C_ 128
#define H_ 96
#define W_ 224

constexpr int TH = 16;
constexpr int TW = 32;
constexpr int CCH = 4;            // channels per pipeline stage
constexpr int NCHUNK = C_ / CCH;  // 32
constexpr int THREADS = 128;      // blockDim = (8,16)
constexpr int RW  = TW + 8;       // 40 padded row
constexpr int S2R_MAX = TH + 2;   // 18 rows buffer (max over dg)
constexpr int F1_F4 = CCH * TH * (TW / 4);        // 512
constexpr int S1BUF = CCH * TH * TW;              // floats per s1 buffer
constexpr int S2BUF = CCH * S2R_MAX * RW;         // floats per s2 buffer

__device__ __forceinline__ void cp_async16(uint32_t dst, const void* src, bool pred) {
    int sz = pred ? 16 : 0;
    asm volatile("cp.async.cg.shared.global [%0], [%1], 16, %2;\n"
                 :: "r"(dst), "l"(src), "r"(sz));
}
__device__ __forceinline__ void cp_commit() {
    asm volatile("cp.async.commit_group;\n" ::);
}
__device__ __forceinline__ void cp_wait1() {
    asm volatile("cp.async.wait_group 1;\n" ::);
}

__device__ __forceinline__ uint64_t pk2(float lo, float hi) {
    uint64_t r; asm("mov.b64 %0, {%1, %2};" : "=l"(r) : "f"(lo), "f"(hi)); return r;
}
__device__ __forceinline__ void fma2(uint64_t& acc, uint64_t a, uint64_t b) {
    asm("fma.rn.f32x2 %0, %1, %2, %0;" : "+l"(acc) : "l"(a), "l"(b));
}
__device__ __forceinline__ void upk(uint64_t v, float& lo, float& hi) {
    asm("mov.b64 {%0, %1}, %2;" : "=f"(lo), "=f"(hi) : "l"(v));
}

template<int DG>
__device__ __forceinline__ void run_tile(
    const float* __restrict__ f1n, const float* __restrict__ f2n,
    float* __restrict__ outn,
    float* s1p, float* s2p,
    int tile_x, int tile_y, int dy0, int tx, int ty, int tid)
{
    constexpr int ROWS  = TH + DG - 1;          // padded f2 rows needed
    constexpr int F2_F4 = CCH * ROWS * (RW / 4);

    const uint32_t s1b = (uint32_t)__cvta_generic_to_shared(s1p);
    const uint32_t s2b = (uint32_t)__cvta_generic_to_shared(s2p);

    // ---- precompute chunk-invariant f2 staging descriptors (6 f4/thread) ----
    int  off2[6];
    int  sm2[6];
    bool pr2[6];
    bool act2[6];
#pragma unroll
    for (int i = 0; i < 6; i++) {
        int idx = tid + THREADS * i;
        act2[i] = (idx < F2_F4);
        int id  = act2[i] ? idx : 0;
        int c   = id / (ROWS * RW / 4);
        int rem = id - c * (ROWS * RW / 4);
        int r   = rem / (RW / 4);
        int q   = rem - r * (RW / 4);
        int gy  = tile_y + dy0 - 4 + r;
        bool valid = ((unsigned)gy < (unsigned)H_)
                   && !(q == 0 && tile_x == 0)
                   && !(q == 9 && tile_x + TW + 4 > W_);
        int gyc = valid ? gy : 0;
        off2[i] = (c * H_ + gyc) * W_ + tile_x - 4 + q * 4;
        if (q == 0 && tile_x == 0) off2[i] += 4;  // keep ptr in-bounds (sz=0)
        sm2[i]  = ((c * S2R_MAX + r) * RW + q * 4) * 4;  // stride = max buffer
        pr2[i]  = valid;
    }

    // packed accumulators: pp=0 -> pixels (0,1), pp=1 -> (2,3)
    uint64_t acc0[DG][9], acc1[DG][9];
#pragma unroll
    for (int d = 0; d < DG; d++)
#pragma unroll
        for (int x = 0; x < 9; x++) { acc0[d][x] = 0ull; acc1[d][x] = 0ull; }

    auto stage = [&](int buf, int cb) {
        const float* f1c = f1n + (size_t)cb * CCH * H_ * W_;
        const float* f2c = f2n + (size_t)cb * CCH * H_ * W_;
        uint32_t d1 = s1b + (uint32_t)(buf * (S1BUF * 4));
        uint32_t d2 = s2b + (uint32_t)(buf * (S2BUF * 4));
#pragma unroll
        for (int i = 0; i < F1_F4 / THREADS; i++) {
            int idx = tid + THREADS * i;
            int c   = idx >> 7;
            int rem = idx & 127;
            int r   = rem >> 3;
            int q   = rem & 7;
            cp_async16(d1 + (uint32_t)(((c * TH + r) * TW + q * 4) * 4),
                       f1c + ((size_t)c * H_ + tile_y + r) * W_ + tile_x + q * 4,
                       true);
        }
#pragma unroll
        for (int i = 0; i < 6; i++) {
            if (act2[i])
                cp_async16(d2 + (uint32_t)sm2[i], f2c + off2[i], pr2[i]);
        }
    };

    // ---- pipeline prologue (depth 2, as R8) ----
    stage(0, 0); cp_commit();
    stage(1, 1); cp_commit();

    for (int cb = 0; cb < NCHUNK; cb++) {
        cp_wait1();
        __syncthreads();

        const int buf = cb & 1;
        const float* s1base = s1p + buf * S1BUF;
        const float* s2base = s2p + buf * S2BUF;

#pragma unroll
        for (int c = 0; c < CCH; c++) {
            uint64_t a01, a23;
            {
                ulonglong2 av = *reinterpret_cast<const ulonglong2*>(
                    s1base + (size_t)(c * TH + ty) * TW + tx * 4);
                a01 = av.x; a23 = av.y;
            }
#pragma unroll
            for (int dyi = 0; dyi < DG; dyi++) {
                const float* row = s2base + (size_t)(c * S2R_MAX + ty + dyi) * RW + tx * 4;
                ulonglong2 e01 = *reinterpret_cast<const ulonglong2*>(row);
                ulonglong2 e23 = *reinterpret_cast<const ulonglong2*>(row + 4);
                ulonglong2 e45 = *reinterpret_cast<const ulonglong2*>(row + 8);
                uint64_t pe[6] = {e01.x, e01.y, e23.x, e23.y, e45.x, e45.y};

                // even-dx fma2s (native pairs, no packs)
#pragma unroll
                for (int dx = 0; dx < 9; dx += 2) {
                    fma2(acc0[dyi][dx], a01, pe[dx >> 1]);
                    fma2(acc1[dyi][dx], a23, pe[(dx >> 1) + 1]);
                }

                // odd pairs: 5 packs from register halves
                float r0, r1, r2, r3, r4, r5, r6, r7, r8, r9, r10, r11;
                upk(pe[0], r0, r1);  upk(pe[1], r2, r3);
                upk(pe[2], r4, r5);  upk(pe[3], r6, r7);
                upk(pe[4], r8, r9);  upk(pe[5], r10, r11);
                uint64_t po[5];
                po[0] = pk2(r1, r2);  po[1] = pk2(r3, r4);
                po[2] = pk2(r5, r6);  po[3] = pk2(r7, r8);
                po[4] = pk2(r9, r10);

#pragma unroll
                for (int dx = 1; dx < 9; dx += 2) {
                    fma2(acc0[dyi][dx], a01, po[dx >> 1]);
                    fma2(acc1[dyi][dx], a23, po[(dx >> 1) + 1]);
                }
            }
        }

        __syncthreads();       // all warps done reading buf before restaging
        if (cb + 2 < NCHUNK) stage(buf, cb + 2);
        cp_commit();           // uniform group accounting
    }

    // ---- epilogue ----
    const float inv = 1.0f / (float)C_;
    const int y = tile_y + ty;
    const int x = tile_x + tx * 4;
#pragma unroll
    for (int dyi = 0; dyi < DG; dyi++)
#pragma unroll
        for (int dx = 0; dx < 9; dx++) {
            int k = (dy0 + dyi) * 9 + dx;
            float v0, v1, v2, v3;
            upk(acc0[dyi][dx], v0, v1);
            upk(acc1[dyi][dx], v2, v3);
            float4 v = make_float4(v0 * inv, v1 * inv, v2 * inv, v3 * inv);
            *reinterpret_cast<float4*>(outn + ((size_t)k * H_ + y) * W_ + x) = v;
        }
}

__global__ __launch_bounds__(THREADS, 3)
void costvol_kernel(const float* __restrict__ f1,
                    const float* __restrict__ f2,
                    float* __restrict__ out)
{
    __shared__ __align__(16) float s1[2][S1BUF];   // 16 KB
    __shared__ __align__(16) float s2[2][S2BUF];   // 23 KB

    const int tx  = threadIdx.x;          // 0..7
    const int ty  = threadIdx.y;          // 0..15
    const int tid = ty * 8 + tx;

    const int tile_x = blockIdx.x * TW;
    const int tile_y = blockIdx.y * TH;
    const int gi     = blockIdx.z & 3;    // dy group: {3,2,2,2} offsets {0,3,5,7}
    const int n      = blockIdx.z >> 2;   // n-major z for L2 locality

    const float* f1n = f1 + (size_t)n * C_ * H_ * W_;
    const float* f2n = f2 + (size_t)n * C_ * H_ * W_;
    float* outn = out + (size_t)n * 81 * H_ * W_;

    if (gi == 0)
        run_tile<3>(f1n, f2n, outn, &s1[0][0], &s2[0][0],
                    tile_x, tile_y, 0, tx, ty, tid);
    else
        run_tile<2>(f1n, f2n, outn, &s1[0][0], &s2[0][0],
                    tile_x, tile_y, 2 * gi + 1, tx, ty, tid);
}

extern "C" void kernel_launch(void* const* d_in, const int* in_sizes, int n_in,
                              void* d_out, int out_size)
{
    const float* f1 = (const float*)d_in[0];
    const float* f2 = (const float*)d_in[1];
    float* out = (float*)d_out;

    dim3 block(8, 16);
    dim3 grid(W_ / TW, H_ / TH, N_ * 4);   // 7 x 6 x 32 = 1344
    costvol_kernel<<<grid, block>>>(f1, f2, out);
}